// round 1
// baseline (speedup 1.0000x reference)
#include <cuda_runtime.h>
#include <math.h>

#define N_SEQ 4096
#define M_SEQ 1024
#define DIMC  512
#define INNER 512
#define HEADS 8
#define DH    64
#define GROUPS 8

// ---------------- scratch (static device globals; no allocation) ----------------
__device__ float g_q[INNER * N_SEQ];          // q[c][i]               8 MB
__device__ float g_pos[GROUPS * M_SEQ];       // sample positions      32 KB
__device__ float g_kvT[2 * M_SEQ * INNER];    // kv[s][t][ch]          4 MB
__device__ float g_k[2 * INNER * M_SEQ];      // k[s][c][t]            4 MB
__device__ float g_v[2 * INNER * M_SEQ];      // v[s][c][t]            4 MB
__device__ float g_att[2 * INNER * N_SEQ];    // attn out [s][c][i]   16 MB

// ================= Kernel 1: grouped 1x1 q projection ==========================
// q[c][i] = sum_{k=0..127} Wq[c*128+k] * src[i*512 + base + k]
// group g = c/64 ; src = prev_x (g<4) or x (g>=4), base = (g&3)*128
__global__ __launch_bounds__(256) void qproj_kernel(
    const float* __restrict__ x, const float* __restrict__ px,
    const float* __restrict__ Wq)
{
    __shared__ float As[16][68];   // As[k][c]
    __shared__ float Bs[16][68];   // Bs[k][i]
    const int g  = blockIdx.y;
    const int i0 = blockIdx.x * 64;
    const int c0 = g * 64;
    const float* src  = (g < 4) ? px : x;
    const int   base  = (g & 3) * 128;
    const int tid = threadIdx.x;
    const int tx = tid & 15, ty = tid >> 4;

    float acc[4][4];
    #pragma unroll
    for (int a = 0; a < 4; a++)
        #pragma unroll
        for (int b = 0; b < 4; b++) acc[a][b] = 0.f;

    for (int k0 = 0; k0 < 128; k0 += 16) {
        {
            int c = tid >> 2, k = (tid & 3) * 4;
            float4 w = *(const float4*)&Wq[(c0 + c) * 128 + k0 + k];
            As[k+0][c] = w.x; As[k+1][c] = w.y; As[k+2][c] = w.z; As[k+3][c] = w.w;
        }
        {
            int i = tid >> 2, k = (tid & 3) * 4;
            float4 b4 = *(const float4*)&src[(i0 + i) * DIMC + base + k0 + k];
            Bs[k+0][i] = b4.x; Bs[k+1][i] = b4.y; Bs[k+2][i] = b4.z; Bs[k+3][i] = b4.w;
        }
        __syncthreads();
        #pragma unroll
        for (int kk = 0; kk < 16; kk++) {
            float a[4], b[4];
            #pragma unroll
            for (int u = 0; u < 4; u++) a[u] = As[kk][ty*4 + u];
            #pragma unroll
            for (int u = 0; u < 4; u++) b[u] = Bs[kk][tx*4 + u];
            #pragma unroll
            for (int ai = 0; ai < 4; ai++)
                #pragma unroll
                for (int bi = 0; bi < 4; bi++) acc[ai][bi] += a[ai] * b[bi];
        }
        __syncthreads();
    }
    #pragma unroll
    for (int ai = 0; ai < 4; ai++)
        #pragma unroll
        for (int bi = 0; bi < 4; bi++)
            g_q[(c0 + ty*4 + ai) * N_SEQ + i0 + tx*4 + bi] = acc[ai][bi];
}

// ================= Kernel 2: offset network ====================================
// depthwise conv (K=6, stride 4, pad 1) -> exact gelu -> pointwise -> tanh*4
// then precompute grid-sample positions
__global__ __launch_bounds__(128) void offset_kernel(
    const float* __restrict__ Wdw, const float* __restrict__ bdw,
    const float* __restrict__ Wp)
{
    const int g = blockIdx.y;
    const int t = blockIdx.x * 128 + threadIdx.x;
    const float* qg = &g_q[g * 64 * N_SEQ];
    const int pbase = 4 * t - 1;
    float s = 0.f;
    for (int c = 0; c < 64; c++) {
        float hv = bdw[c];
        const float* qr = &qg[c * N_SEQ];
        #pragma unroll
        for (int k = 0; k < 6; k++) {
            int p = pbase + k;
            if (p >= 0 && p < N_SEQ) hv += Wdw[c * 6 + k] * qr[p];
        }
        hv = 0.5f * hv * (1.f + erff(hv * 0.7071067811865476f));  // exact gelu
        s += Wp[c] * hv;
    }
    float off = tanhf(s) * 4.0f;
    float vg  = 2.0f * ((float)t + off) / 1023.0f - 1.0f;
    float pos = ((vg + 1.0f) * (float)N_SEQ - 1.0f) * 0.5f;
    g_pos[g * M_SEQ + t] = pos;
}

// ================= Kernel 3: 1-D bilinear grid sample ==========================
// g_kvT[s][t][ch] so k/v GEMMs get coalesced B tiles
__global__ __launch_bounds__(256) void gridsample_kernel(
    const float* __restrict__ x, const float* __restrict__ px)
{
    const int tid = blockIdx.x * 256 + threadIdx.x;   // 2*8*1024*64 total
    const int c    = tid & 63;
    const int unit = tid >> 6;
    const int t  = unit & (M_SEQ - 1);
    const int sg = unit >> 10;
    const int g  = sg & 7;
    const int s  = sg >> 3;
    const float* src = (s == 0) ? px : x;
    const float pos = g_pos[g * M_SEQ + t];
    const float x0 = floorf(pos);
    const float w1 = pos - x0;
    const int p0 = (int)x0;
    const int ch = g * 64 + c;
    float v = 0.f;
    if (p0 >= 0 && p0 < N_SEQ)           v += (1.f - w1) * src[p0 * DIMC + ch];
    if (p0 + 1 >= 0 && p0 + 1 < N_SEQ)   v += w1 * src[(p0 + 1) * DIMC + ch];
    g_kvT[(s * M_SEQ + t) * INNER + ch] = v;
}

// ================= Kernel 4: grouped 1x1 k/v projection ========================
// out[s][c][t] = sum_{j=0..63} W[c*64+j] * g_kvT[s][t][g*64+j]
__global__ __launch_bounds__(256) void kvproj_kernel(
    const float* __restrict__ W, int which)   // which: 0 -> g_k, 1 -> g_v
{
    __shared__ float As[16][68];
    __shared__ float Bs[16][68];
    const int g  = blockIdx.y;
    const int s  = blockIdx.z;
    const int t0 = blockIdx.x * 64;
    const int c0 = g * 64;
    const int tid = threadIdx.x;
    const int tx = tid & 15, ty = tid >> 4;
    const float* kvb = &g_kvT[s * M_SEQ * INNER];
    float* out = (which ? g_v : g_k) + s * INNER * M_SEQ;

    float acc[4][4];
    #pragma unroll
    for (int a = 0; a < 4; a++)
        #pragma unroll
        for (int b = 0; b < 4; b++) acc[a][b] = 0.f;

    for (int k0 = 0; k0 < 64; k0 += 16) {
        {
            int c = tid >> 2, k = (tid & 3) * 4;
            float4 w = *(const float4*)&W[(c0 + c) * 64 + k0 + k];
            As[k+0][c] = w.x; As[k+1][c] = w.y; As[k+2][c] = w.z; As[k+3][c] = w.w;
        }
        {
            int t = tid >> 2, k = (tid & 3) * 4;
            float4 b4 = *(const float4*)&kvb[(t0 + t) * INNER + c0 + k0 + k];
            Bs[k+0][t] = b4.x; Bs[k+1][t] = b4.y; Bs[k+2][t] = b4.z; Bs[k+3][t] = b4.w;
        }
        __syncthreads();
        #pragma unroll
        for (int kk = 0; kk < 16; kk++) {
            float a[4], b[4];
            #pragma unroll
            for (int u = 0; u < 4; u++) a[u] = As[kk][ty*4 + u];
            #pragma unroll
            for (int u = 0; u < 4; u++) b[u] = Bs[kk][tx*4 + u];
            #pragma unroll
            for (int ai = 0; ai < 4; ai++)
                #pragma unroll
                for (int bi = 0; bi < 4; bi++) acc[ai][bi] += a[ai] * b[bi];
        }
        __syncthreads();
    }
    #pragma unroll
    for (int ai = 0; ai < 4; ai++)
        #pragma unroll
        for (int bi = 0; bi < 4; bi++)
            out[(c0 + ty*4 + ai) * M_SEQ + t0 + tx*4 + bi] = acc[ai][bi];
}

// ================= Kernel 5: flash-style attention =============================
// per (stream, head): Q (4096x64) x K (1024x64)^T -> softmax -> x V (1024x64)
__global__ __launch_bounds__(128) void attn_kernel()
{
    __shared__ float Qs[64][68];
    __shared__ float Ks[64][68];
    __shared__ float Vs[64][68];
    __shared__ float Ps[64][68];
    const int i0 = blockIdx.x * 64;
    const int h  = blockIdx.y;
    const int s  = blockIdx.z;
    const int tid = threadIdx.x;
    const int tx = tid & 15, ty = tid >> 4;

    const float* qb = &g_q[h * 64 * N_SEQ];
    for (int idx = tid; idx < 4096; idx += 128) {
        int d = idx >> 6, i = idx & 63;
        Qs[d][i] = qb[d * N_SEQ + i0 + i] * 0.125f;   // DIM_HEAD^-0.5
    }
    const float* kb = &g_k[s * INNER * M_SEQ + h * 64 * M_SEQ];
    const float* vb = &g_v[s * INNER * M_SEQ + h * 64 * M_SEQ];

    float m_i[8], l_i[8], acc[8][4];
    #pragma unroll
    for (int a = 0; a < 8; a++) {
        m_i[a] = -1e30f; l_i[a] = 0.f;
        #pragma unroll
        for (int b = 0; b < 4; b++) acc[a][b] = 0.f;
    }

    for (int j0 = 0; j0 < M_SEQ; j0 += 64) {
        __syncthreads();   // previous PV / Q writes done
        for (int idx = tid; idx < 4096; idx += 128) {
            int d = idx >> 6, j = idx & 63;
            float kvv = kb[d * M_SEQ + j0 + j];
            float vvv = vb[d * M_SEQ + j0 + j];
            Ks[d][j] = kvv;
            Vs[j][d] = vvv;
        }
        __syncthreads();

        // S = Q^T K tile (64x64), thread owns 8 rows x 4 cols
        float sv[8][4];
        #pragma unroll
        for (int a = 0; a < 8; a++)
            #pragma unroll
            for (int b = 0; b < 4; b++) sv[a][b] = 0.f;
        #pragma unroll 4
        for (int kk = 0; kk < 64; kk++) {
            float4 q0 = *(const float4*)&Qs[kk][ty * 8];
            float4 q1 = *(const float4*)&Qs[kk][ty * 8 + 4];
            float4 kr = *(const float4*)&Ks[kk][tx * 4];
            float qr[8] = {q0.x, q0.y, q0.z, q0.w, q1.x, q1.y, q1.z, q1.w};
            float br[4] = {kr.x, kr.y, kr.z, kr.w};
            #pragma unroll
            for (int a = 0; a < 8; a++)
                #pragma unroll
                for (int b = 0; b < 4; b++) sv[a][b] += qr[a] * br[b];
        }

        // online softmax update (row reductions across the 16 tx lanes)
        #pragma unroll
        for (int a = 0; a < 8; a++) {
            float mx = fmaxf(fmaxf(sv[a][0], sv[a][1]), fmaxf(sv[a][2], sv[a][3]));
            #pragma unroll
            for (int o = 8; o >= 1; o >>= 1)
                mx = fmaxf(mx, __shfl_xor_sync(0xffffffffu, mx, o));
            float mnew = fmaxf(m_i[a], mx);
            float corr = __expf(m_i[a] - mnew);
            float rsum = 0.f;
            float4 pv;
            float p0 = __expf(sv[a][0] - mnew);
            float p1 = __expf(sv[a][1] - mnew);
            float p2 = __expf(sv[a][2] - mnew);
            float p3 = __expf(sv[a][3] - mnew);
            pv.x = p0; pv.y = p1; pv.z = p2; pv.w = p3;
            rsum = p0 + p1 + p2 + p3;
            *(float4*)&Ps[ty * 8 + a][tx * 4] = pv;
            #pragma unroll
            for (int o = 8; o >= 1; o >>= 1)
                rsum += __shfl_xor_sync(0xffffffffu, rsum, o);
            l_i[a] = l_i[a] * corr + rsum;
            m_i[a] = mnew;
            #pragma unroll
            for (int b = 0; b < 4; b++) acc[a][b] *= corr;
        }
        __syncthreads();

        // acc += P x V
        #pragma unroll 4
        for (int j = 0; j < 64; j++) {
            float4 vr4 = *(const float4*)&Vs[j][tx * 4];
            float vr[4] = {vr4.x, vr4.y, vr4.z, vr4.w};
            #pragma unroll
            for (int a = 0; a < 8; a++) {
                float p = Ps[ty * 8 + a][j];
                #pragma unroll
                for (int b = 0; b < 4; b++) acc[a][b] += p * vr[b];
            }
        }
    }
    __syncthreads();
    // stage output through smem (reuse Ks) for coalesced store
    #pragma unroll
    for (int a = 0; a < 8; a++) {
        float inv = 1.f / l_i[a];
        #pragma unroll
        for (int b = 0; b < 4; b++)
            Ks[tx * 4 + b][ty * 8 + a] = acc[a][b] * inv;
    }
    __syncthreads();
    float* ob = &g_att[s * INNER * N_SEQ + h * 64 * N_SEQ];
    for (int idx = tid; idx < 4096; idx += 128) {
        int d = idx >> 6, i = idx & 63;
        ob[d * N_SEQ + i0 + i] = Ks[d][i];
    }
}

// ================= Kernel 6: stream-mean + Wo GEMM + bias ======================
// y[i][d] = bo[d] + sum_c Wo[d*512+c] * 0.5*(g_att[0][c][i]+g_att[1][c][i])
__global__ __launch_bounds__(256) void outproj_kernel(
    const float* __restrict__ Wo, const float* __restrict__ bo,
    float* __restrict__ out)
{
    __shared__ float As[16][68];
    __shared__ float Bs[16][68];
    const int d0 = blockIdx.y * 64;
    const int i0 = blockIdx.x * 64;
    const int tid = threadIdx.x;
    const int tx = tid & 15, ty = tid >> 4;

    float acc[4][4];
    #pragma unroll
    for (int a = 0; a < 4; a++)
        #pragma unroll
        for (int b = 0; b < 4; b++) acc[a][b] = 0.f;

    for (int k0 = 0; k0 < 512; k0 += 16) {
        {
            int d = tid >> 2, k = (tid & 3) * 4;
            float4 w = *(const float4*)&Wo[(d0 + d) * INNER + k0 + k];
            As[k+0][d] = w.x; As[k+1][d] = w.y; As[k+2][d] = w.z; As[k+3][d] = w.w;
        }
        {
            int k = tid >> 4, i4 = (tid & 15) * 4;
            const float* a0 = &g_att[(k0 + k) * N_SEQ + i0 + i4];
            const float* a1 = a0 + INNER * N_SEQ;
            float4 v0 = *(const float4*)a0;
            float4 v1 = *(const float4*)a1;
            Bs[k][i4+0] = 0.5f * (v0.x + v1.x);
            Bs[k][i4+1] = 0.5f * (v0.y + v1.y);
            Bs[k][i4+2] = 0.5f * (v0.z + v1.z);
            Bs[k][i4+3] = 0.5f * (v0.w + v1.w);
        }
        __syncthreads();
        #pragma unroll
        for (int kk = 0; kk < 16; kk++) {
            float a[4], b[4];
            #pragma unroll
            for (int u = 0; u < 4; u++) a[u] = As[kk][ty*4 + u];
            #pragma unroll
            for (int u = 0; u < 4; u++) b[u] = Bs[kk][tx*4 + u];
            #pragma unroll
            for (int ai = 0; ai < 4; ai++)
                #pragma unroll
                for (int bi = 0; bi < 4; bi++) acc[ai][bi] += a[ai] * b[bi];
        }
        __syncthreads();
    }
    #pragma unroll
    for (int ai = 0; ai < 4; ai++) {
        float bias = bo[d0 + ty*4 + ai];
        #pragma unroll
        for (int bi = 0; bi < 4; bi++)
            out[(i0 + tx*4 + bi) * DIMC + d0 + ty*4 + ai] = acc[ai][bi] + bias;
    }
}

// ================= launch ======================================================
extern "C" void kernel_launch(void* const* d_in, const int* in_sizes, int n_in,
                              void* d_out, int out_size)
{
    const float* x   = (const float*)d_in[0];
    const float* px  = (const float*)d_in[1];
    const float* Wq  = (const float*)d_in[2];
    const float* Wk  = (const float*)d_in[3];
    const float* Wv  = (const float*)d_in[4];
    const float* Wo  = (const float*)d_in[5];
    const float* bo  = (const float*)d_in[6];
    const float* Wdw = (const float*)d_in[7];
    const float* bdw = (const float*)d_in[8];
    const float* Wp  = (const float*)d_in[9];
    float* out = (float*)d_out;

    qproj_kernel<<<dim3(64, 8), 256>>>(x, px, Wq);
    offset_kernel<<<dim3(8, 8), 128>>>(Wdw, bdw, Wp);
    gridsample_kernel<<<4096, 256>>>(x, px);
    kvproj_kernel<<<dim3(16, 8, 2), 256>>>(Wk, 0);
    kvproj_kernel<<<dim3(16, 8, 2), 256>>>(Wv, 1);
    attn_kernel<<<dim3(64, HEADS, 2), 128>>>();
    outproj_kernel<<<dim3(64, 8), 256>>>(Wo, bo, out);
}